// round 9
// baseline (speedup 1.0000x reference)
#include <cuda_runtime.h>
#include <cuda_fp16.h>
#include <cstdint>
#include <cstddef>

// ---------------------------------------------------------------------------
// RNN_fish, persistent HMMA kernel, single fp16 chain:
//   h_t = 0.8*h_{t-1} + (g.h_{t-1}) @ (0.2*wrec^T) + U_t
// R9: phase-2 owned by k-slice groups (16 CTAs each) -> 2nd barrier is a
// 16-CTA sub-barrier, not global; h carried in registers per owner thread.
// ---------------------------------------------------------------------------

namespace {
constexpr int Bn = 64;
constexpr int Sn = 512;
constexpr int In = 128;
constexpr int Hn = 2048;
constexpr int On = 128;
constexpr int KSPLIT = 9;
constexpr int NCTA = 144;             // 16 j-tiles x 9 k-slices
constexpr int NTHR = 512;             // 16 warps
constexpr int HB = Hn * Bn;
constexpr float kNoise = 0.005f;
constexpr float kAlpha = 0.2f;

// k16-units per slice: slices 0,1 get 15, slices 2..8 get 14 (2*15+7*14=128)
__host__ __device__ __forceinline__ int slice_units(int kq) { return 14 + (kq < 2); }
__host__ __device__ __forceinline__ int slice_start16(int kq) {
    return kq * 14 + (kq < 2 ? kq : 2);
}

// smem layout (bytes). Rows padded to 528B -> conflict-free ldmatrix.
constexpr int ROWB = 528;
constexpr int OFF_WH = 0;                       // 128*528 = 67584
constexpr int OFF_BH = OFF_WH + 128 * ROWB;     // 67584 (+64*528 = 33792)
constexpr int OFF_RED = OFF_BH;                 // pair-reduce stage overlay, 40960
constexpr int OFF_STG = OFF_RED + 40960;        // +15*66*4 = 3960
constexpr int SMEM_TOTAL = OFF_STG + 4224;      // 112768
}

// device globals (allocation-free rule)
__device__ float g_h[(size_t)Sn * Hn * Bn];          // [t][j][b]
__device__ float g_U[(size_t)Sn * Hn * Bn];          // [t][j][b] (t>=1)
__device__ float g_part[(size_t)KSPLIT * Hn * Bn];   // [q][j][b]
__device__ __half g_Wh[(size_t)Hn * Hn];             // [j][k] fp16 of 0.2*g[k]*wrec[j][k]
__device__ __half g_hb[(size_t)Bn * Hn];             // [b][k] fp16 h_{t-1}
__device__ unsigned g_bar_count;
__device__ unsigned g_bar_gen;
__device__ unsigned g_sub[KSPLIT * 32];              // per-kq: count @+0, gen @+16

// ---- helpers ----
__device__ __forceinline__ uint32_t smem_u32(const void* p) {
    uint32_t a;
    asm("{ .reg .u64 t; cvta.to.shared.u64 t, %1; cvt.u32.u64 %0, t; }" : "=r"(a) : "l"(p));
    return a;
}
__device__ __forceinline__ void ldsm4(uint32_t a[4], uint32_t addr) {
    asm volatile("ldmatrix.sync.aligned.m8n8.x4.shared.b16 {%0,%1,%2,%3}, [%4];"
                 : "=r"(a[0]), "=r"(a[1]), "=r"(a[2]), "=r"(a[3]) : "r"(addr));
}
__device__ __forceinline__ void mma16816(float c[4], const uint32_t a[4],
                                         uint32_t b0, uint32_t b1) {
    asm volatile("mma.sync.aligned.m16n8k16.row.col.f32.f16.f16.f32 "
                 "{%0,%1,%2,%3}, {%4,%5,%6,%7}, {%8,%9}, {%0,%1,%2,%3};"
                 : "+f"(c[0]), "+f"(c[1]), "+f"(c[2]), "+f"(c[3])
                 : "r"(a[0]), "r"(a[1]), "r"(a[2]), "r"(a[3]), "r"(b0), "r"(b1));
}
__device__ __forceinline__ void ffma2(unsigned long long &acc, unsigned long long a,
                                      unsigned long long b) {
    asm("fma.rn.f32x2 %0, %1, %2, %0;" : "+l"(acc) : "l"(a), "l"(b));
}
__device__ __forceinline__ unsigned long long splat2(float w) {
    unsigned long long r;
    asm("mov.b64 %0, {%1, %1};" : "=l"(r) : "f"(w));
    return r;
}
__device__ __forceinline__ float2 unpack2(unsigned long long v) {
    float2 r;
    asm("mov.b64 {%0, %1}, %2;" : "=f"(r.x), "=f"(r.y) : "l"(v));
    return r;
}

// global grid barrier (replay-deterministic) -- proven, unchanged
__device__ __forceinline__ void grid_sync_dev() {
    __syncthreads();
    if (threadIdx.x == 0) {
        __threadfence();
        unsigned old, my;
        asm volatile("ld.acquire.gpu.global.u32 %0, [%1];"
                     : "=r"(old) : "l"(&g_bar_gen) : "memory");
        asm volatile("atom.release.gpu.global.add.u32 %0, [%1], %2;"
                     : "=r"(my) : "l"(&g_bar_count), "r"(1u) : "memory");
        if (my == (unsigned)(NCTA - 1)) {
            asm volatile("st.global.u32 [%0], %1;" :: "l"(&g_bar_count), "r"(0u) : "memory");
            asm volatile("red.release.gpu.global.add.u32 [%0], %1;"
                         :: "l"(&g_bar_gen), "r"(1u) : "memory");
        } else {
            unsigned cur;
            do {
                asm volatile("ld.acquire.gpu.global.u32 %0, [%1];"
                             : "=r"(cur) : "l"(&g_bar_gen) : "memory");
            } while (cur == old);
        }
        __threadfence();
    }
    __syncthreads();
}

// 16-CTA sub-barrier for one kq group (same protocol, per-group counters)
__device__ __forceinline__ void sub_sync_dev(int kq) {
    __syncthreads();
    if (threadIdx.x == 0) {
        unsigned* cnt = &g_sub[kq * 32];
        unsigned* gen = &g_sub[kq * 32 + 16];
        __threadfence();
        unsigned old, my;
        asm volatile("ld.acquire.gpu.global.u32 %0, [%1];"
                     : "=r"(old) : "l"(gen) : "memory");
        asm volatile("atom.release.gpu.global.add.u32 %0, [%1], %2;"
                     : "=r"(my) : "l"(cnt), "r"(1u) : "memory");
        if (my == 15u) {
            asm volatile("st.global.u32 [%0], %1;" :: "l"(cnt), "r"(0u) : "memory");
            asm volatile("red.release.gpu.global.add.u32 [%0], %1;"
                         :: "l"(gen), "r"(1u) : "memory");
        } else {
            unsigned cur;
            do {
                asm volatile("ld.acquire.gpu.global.u32 %0, [%1];"
                             : "=r"(cur) : "l"(gen) : "memory");
            } while (cur == old);
        }
        __threadfence();
    }
    __syncthreads();
}

// ---------------------------------------------------------------------------
// prep kernels
// ---------------------------------------------------------------------------
__global__ void wprep_kernel(const float* __restrict__ wrec, const float* __restrict__ g) {
    int n = blockIdx.x * blockDim.x + threadIdx.x;      // < Hn*Hn  ([j][k])
    int k = n & (Hn - 1);
    g_Wh[n] = __float2half_rn(kAlpha * g[k] * wrec[n]);
}

__global__ void hinit_kernel(const float* __restrict__ h0) {
    int n = blockIdx.x * blockDim.x + threadIdx.x;      // < Hn*Bn, [j][b]
    g_h[n] = h0[n >> 6];
}

__global__ void hbinit_kernel(const float* __restrict__ h0) {
    int n = blockIdx.x * blockDim.x + threadIdx.x;      // < Bn*Hn, [b][k]
    g_hb[n] = __float2half_rn(h0[n & (Hn - 1)]);
}

// ---------------------------------------------------------------------------
// U[t][j][b] = alpha * x[b][t-1]@wi[:,j] + noise_std*noise[b][t-1][j]
// ---------------------------------------------------------------------------
__global__ __launch_bounds__(256) void u_kernel(const float* __restrict__ x,
                                                const float* __restrict__ noise,
                                                const float* __restrict__ wi) {
    __shared__ float As[64][66];
    __shared__ float Ws[64][64];
    int t = blockIdx.y + 1;
    int j0 = blockIdx.x * 64;
    int tid = threadIdx.x;
    int by = tid & 15, jx = tid >> 4;
    int b0 = by * 4;
    unsigned long long acc[4][2] = {};

    for (int i0 = 0; i0 < In; i0 += 64) {
        #pragma unroll
        for (int p = 0; p < 16; p++) {
            int f = tid + p * 256;
            int i = f & 63, b = f >> 6;
            As[i][b] = x[((size_t)b * Sn + (t - 1)) * In + i0 + i];
        }
        #pragma unroll
        for (int p = 0; p < 4; p++) {
            int f = tid + p * 256;
            int i = f >> 4, c = f & 15;
            *(float4*)&Ws[i][c * 4] = *(const float4*)&wi[(size_t)(i0 + i) * Hn + j0 + c * 4];
        }
        __syncthreads();
        #pragma unroll 16
        for (int k = 0; k < 64; k++) {
            const unsigned long long* ap = (const unsigned long long*)&As[k][b0];
            unsigned long long a01 = ap[0], a23 = ap[1];
            float4 w = *(const float4*)&Ws[k][jx * 4];
            unsigned long long w0 = splat2(w.x), w1 = splat2(w.y),
                               w2 = splat2(w.z), w3 = splat2(w.w);
            ffma2(acc[0][0], a01, w0); ffma2(acc[0][1], a23, w0);
            ffma2(acc[1][0], a01, w1); ffma2(acc[1][1], a23, w1);
            ffma2(acc[2][0], a01, w2); ffma2(acc[2][1], a23, w2);
            ffma2(acc[3][0], a01, w3); ffma2(acc[3][1], a23, w3);
        }
        __syncthreads();
    }
    #pragma unroll
    for (int jj = 0; jj < 4; jj++) {
        int j = j0 + jx * 4 + jj;
        float2 lo = unpack2(acc[jj][0]), hi = unpack2(acc[jj][1]);
        float4 v;
        v.x = kAlpha * lo.x + kNoise * noise[((size_t)(b0 + 0) * Sn + (t - 1)) * Hn + j];
        v.y = kAlpha * lo.y + kNoise * noise[((size_t)(b0 + 1) * Sn + (t - 1)) * Hn + j];
        v.z = kAlpha * hi.x + kNoise * noise[((size_t)(b0 + 2) * Sn + (t - 1)) * Hn + j];
        v.w = kAlpha * hi.y + kNoise * noise[((size_t)(b0 + 3) * Sn + (t - 1)) * Hn + j];
        *(float4*)&g_U[((size_t)t * Hn + j) * Bn + b0] = v;
    }
}

// ---------------------------------------------------------------------------
// persistent HMMA loop. CTA (jt,kq): partial D[128j x 64b] over its k-slice.
// Phase 2: CTA (jt,kq) owns j in [kbase + jt*ku, +ku) -- the h-slice consumed
// as next-step B by its own kq group. 2nd barrier = 16-CTA sub-barrier.
// h carried in registers (fixed (j,b) ownership per thread).
// ---------------------------------------------------------------------------
__global__ __launch_bounds__(NTHR, 1) void loop_kernel(const float* __restrict__ h0) {
    extern __shared__ char smem[];
    const uint32_t sb = smem_u32(smem);
    const int tid = threadIdx.x;
    const int wid = tid >> 5, lane = tid & 31;
    const int cta = blockIdx.x;
    const int jt = cta / KSPLIT, kq = cta % KSPLIT;
    const int j0 = jt * 128;
    const int ku = slice_units(kq);           // 14 or 15
    const int ku2 = ku * 2;                   // 16B chunks per row
    const int kbase = slice_start16(kq) * 16; // element base
    const int u0 = (ku + 1) >> 1;             // khalf0 units (7 or 8)

    const int tile = wid >> 1;                // 0..7
    const int khalf = wid & 1;
    const int mg = tile >> 1;                 // 0..3 (32 j each)
    const int nh = tile & 1;                  // 0..1 (32 b each)
    const int myU = khalf ? (ku - u0) : u0;   // k16-units for this warp
    const uint32_t koff = (uint32_t)(khalf ? u0 * 32 : 0);

    // phase-2 ownership: ku j-rows starting at jown0
    const int jown0 = kbase + jt * ku;
    const bool own = (tid < ku * 32);         // tid*2 < ku*64 elements
    const int jl = (tid * 2) >> 6;            // 0..ku-1
    const int bb = (tid * 2) & 63;
    const size_t ownIdx = (size_t)(jown0 + jl) * Bn + bb;

    // register-resident h for owned elements (h_0 = h0[j] broadcast over b)
    float2 hreg = make_float2(0.f, 0.f);
    if (own) { float v = h0[jown0 + jl]; hreg = make_float2(v, v); }

    // ---- prologue: resident W -> SMEM (padded rows) ----
    for (int p = 0; p < 8; p++) {
        int f = tid + p * 512;                // < 4096
        int r = f >> 5, c = f & 31;
        if (c < ku2)
            *(uint4*)(smem + OFF_WH + r * ROWB + c * 16) =
                *(const uint4*)&g_Wh[(size_t)(j0 + r) * Hn + kbase + c * 8];
    }
    __syncthreads();

    // per-lane ldmatrix addresses (byte offsets within W/B blocks)
    const uint32_t aLane =
        (uint32_t)(mg * 32 + (lane & 15)) * ROWB + koff + (lane >> 4) * 16;
    const uint32_t bLane =
        (uint32_t)(nh * 32 + (lane & 7) + ((lane >> 4) & 1) * 8) * ROWB +
        koff + ((lane >> 3) & 1) * 16;
    const int g8 = lane >> 2, tg = lane & 3;
    float* red = (float*)(smem + OFF_RED) + tile * 1280;   // 32 rows x 40 floats
    float (*stage)[66] = (float (*)[66])(smem + OFF_STG);  // [ku<=15][64+pad]

    for (int t = 1; t < Sn; t++) {
        // ---- load B (fp16 h slice, produced by this kq group) ----
        #pragma unroll
        for (int p = 0; p < 4; p++) {
            int f = tid + p * 512;            // < 2048
            int b = f >> 5, c = f & 31;
            if (c < ku2)
                *(uint4*)(smem + OFF_BH + b * ROWB + c * 16) =
                    __ldcg((const uint4*)&g_hb[(size_t)b * Hn + kbase + c * 8]);
        }
        __syncthreads();

        // ---- single mma chain ----
        float acc1[2][4][4] = {};
        {
            const uint32_t aHi = sb + OFF_WH + aLane;
            const uint32_t bBase = sb + OFF_BH + bLane;
            #pragma unroll 4
            for (int kk = 0; kk < myU; kk++) {
                uint32_t Bv[4], Bw[4], A0[4], A1[4];
                ldsm4(Bv, bBase + kk * 32);
                ldsm4(Bw, bBase + kk * 32 + 16 * ROWB);
                ldsm4(A0, aHi + kk * 32);
                ldsm4(A1, aHi + kk * 32 + 16 * ROWB);
                mma16816(acc1[0][0], A0, Bv[0], Bv[1]);
                mma16816(acc1[0][1], A0, Bv[2], Bv[3]);
                mma16816(acc1[0][2], A0, Bw[0], Bw[1]);
                mma16816(acc1[0][3], A0, Bw[2], Bw[3]);
                mma16816(acc1[1][0], A1, Bv[0], Bv[1]);
                mma16816(acc1[1][1], A1, Bv[2], Bv[3]);
                mma16816(acc1[1][2], A1, Bw[0], Bw[1]);
                mma16816(acc1[1][3], A1, Bw[2], Bw[3]);
            }
        }
        __syncthreads();   // all warps done reading B (red overlays BH)

        // ---- pair-reduce k halves, write g_part ----
        if (khalf) {
            #pragma unroll
            for (int mt = 0; mt < 2; mt++)
                #pragma unroll
                for (int nt = 0; nt < 4; nt++) {
                    int r0 = mt * 16 + g8, cc = nt * 8 + tg * 2;
                    *(float2*)&red[r0 * 40 + cc] =
                        make_float2(acc1[mt][nt][0], acc1[mt][nt][1]);
                    *(float2*)&red[(r0 + 8) * 40 + cc] =
                        make_float2(acc1[mt][nt][2], acc1[mt][nt][3]);
                }
        }
        __syncthreads();
        if (!khalf) {
            #pragma unroll
            for (int mt = 0; mt < 2; mt++)
                #pragma unroll
                for (int nt = 0; nt < 4; nt++) {
                    int r0 = mt * 16 + g8, cc = nt * 8 + tg * 2;
                    float2 p0 = *(float2*)&red[r0 * 40 + cc];
                    float2 p1 = *(float2*)&red[(r0 + 8) * 40 + cc];
                    int j = j0 + mg * 32 + r0;
                    int bc = nh * 32 + cc;
                    __stcg((float2*)&g_part[((size_t)kq * Hn + j) * Bn + bc],
                           make_float2(acc1[mt][nt][0] + p0.x, acc1[mt][nt][1] + p0.y));
                    __stcg((float2*)&g_part[((size_t)kq * Hn + j + 8) * Bn + bc],
                           make_float2(acc1[mt][nt][2] + p1.x, acc1[mt][nt][3] + p1.y));
                }
        }

        // ---- prefetch phase-2 U (barrier-independent) ----
        float2 uu = make_float2(0.f, 0.f);
        if (own) uu = *(const float2*)&g_U[(size_t)t * HB + ownIdx];

        grid_sync_dev();   // all partials visible

        // ---- phase 2: reduce 9 k-slices + leak + U on owned (j,b) ----
        if (own) {
            float2 s = make_float2(0.f, 0.f);
            #pragma unroll
            for (int q = 0; q < KSPLIT; q++) {
                float2 v = __ldcg((const float2*)&g_part[(size_t)q * HB + ownIdx]);
                s.x += v.x; s.y += v.y;
            }
            float2 hn = make_float2((1.f - kAlpha) * hreg.x + s.x + uu.x,
                                    (1.f - kAlpha) * hreg.y + s.y + uu.y);
            hreg = hn;
            *(float2*)&g_h[(size_t)t * HB + ownIdx] = hn;
            *(float2*)&stage[jl][bb] = hn;
        }
        __syncthreads();
        {
            // transposed fp16 write: hb[b][jown0 + jj]
            int b = tid >> 3, kk = (tid & 7) * 2;
            if (kk < ku)
                g_hb[(size_t)b * Hn + jown0 + kk] = __float2half_rn(stage[kk][b]);
            if (kk + 1 < ku)
                g_hb[(size_t)b * Hn + jown0 + kk + 1] = __float2half_rn(stage[kk + 1][b]);
        }

        sub_sync_dev(kq);  // h-slice kq visible to its 16 consumer CTAs
    }
}

// ---------------------------------------------------------------------------
// out[b][t][o] = sum_k g_h[t][k][b] * wout[k][o]
// ---------------------------------------------------------------------------
__global__ __launch_bounds__(256) void out_kernel(const float* __restrict__ wout,
                                                  float* __restrict__ out) {
    __shared__ float As[32][Bn];
    __shared__ float Ws[32][On];
    int t = blockIdx.x;
    int tid = threadIdx.x;
    int ox = tid & 31, by = tid >> 5;
    int o0 = ox * 4, b0 = by * 8;
    unsigned long long acc[4][4] = {};

    const float* hsrc = g_h + (size_t)t * HB;
    for (int k0 = 0; k0 < Hn; k0 += 32) {
        const float4* asrc = (const float4*)(hsrc + (size_t)k0 * Bn);
        float4* adst = (float4*)&As[0][0];
        #pragma unroll
        for (int p = 0; p < 2; p++) adst[tid + p * 256] = asrc[tid + p * 256];
        #pragma unroll
        for (int p = 0; p < 4; p++) {
            int f = tid + p * 256;
            int k = f >> 5, c = f & 31;
            *(float4*)&Ws[k][c * 4] = *(const float4*)&wout[(size_t)(k0 + k) * On + c * 4];
        }
        __syncthreads();
        #pragma unroll 8
        for (int k = 0; k < 32; k++) {
            const unsigned long long* ap = (const unsigned long long*)&As[k][b0];
            unsigned long long a01 = ap[0], a23 = ap[1], a45 = ap[2], a67 = ap[3];
            float4 w = *(const float4*)&Ws[k][o0];
            unsigned long long w0 = splat2(w.x), w1 = splat2(w.y),
                               w2 = splat2(w.z), w3 = splat2(w.w);
            ffma2(acc[0][0], a01, w0); ffma2(acc[0][1], a01, w1);
            ffma2(acc[0][2], a01, w2); ffma2(acc[0][3], a01, w3);
            ffma2(acc[1][0], a23, w0); ffma2(acc[1][1], a23, w1);
            ffma2(acc[1][2], a23, w2); ffma2(acc[1][3], a23, w3);
            ffma2(acc[2][0], a45, w0); ffma2(acc[2][1], a45, w1);
            ffma2(acc[2][2], a45, w2); ffma2(acc[2][3], a45, w3);
            ffma2(acc[3][0], a67, w0); ffma2(acc[3][1], a67, w1);
            ffma2(acc[3][2], a67, w2); ffma2(acc[3][3], a67, w3);
        }
        __syncthreads();
    }
    #pragma unroll
    for (int bp = 0; bp < 4; bp++) {
        float2 u0 = unpack2(acc[bp][0]), u1 = unpack2(acc[bp][1]);
        float2 u2 = unpack2(acc[bp][2]), u3 = unpack2(acc[bp][3]);
        int b = b0 + bp * 2;
        *(float4*)&out[((size_t)b * Sn + t) * On + o0] = make_float4(u0.x, u1.x, u2.x, u3.x);
        *(float4*)&out[((size_t)(b + 1) * Sn + t) * On + o0] =
            make_float4(u0.y, u1.y, u2.y, u3.y);
    }
}

// ---------------------------------------------------------------------------
extern "C" void kernel_launch(void* const* d_in, const int* in_sizes, int n_in,
                              void* d_out, int out_size) {
    const float* x     = (const float*)d_in[0];
    const float* noise = (const float*)d_in[1];
    const float* wi    = (const float*)d_in[2];
    const float* wrec  = (const float*)d_in[3];
    const float* wout  = (const float*)d_in[4];
    const float* g     = (const float*)d_in[5];
    const float* h0    = (const float*)d_in[6];
    float* out = (float*)d_out;

    cudaFuncSetAttribute(loop_kernel, cudaFuncAttributeMaxDynamicSharedMemorySize,
                         SMEM_TOTAL);

    wprep_kernel<<<Hn * Hn / 256, 256>>>(wrec, g);
    u_kernel<<<dim3(Hn / 64, Sn - 1), 256>>>(x, noise, wi);
    hinit_kernel<<<HB / 256, 256>>>(h0);
    hbinit_kernel<<<HB / 256, 256>>>(h0);
    loop_kernel<<<NCTA, NTHR, SMEM_TOTAL>>>(h0);
    out_kernel<<<Sn, 256>>>(wout, out);
}

// round 10
// speedup vs baseline: 1.1112x; 1.1112x over previous
#include <cuda_runtime.h>
#include <cuda_fp16.h>
#include <cstdint>
#include <cstddef>

// ---------------------------------------------------------------------------
// RNN_fish, persistent HMMA kernel, single fp16 chain (R8 loop structure):
//   h_t = 0.8*h_{t-1} + (g.h_{t-1}) @ (0.2*wrec^T) + U_t
// R10: h carried in registers; fp16 h history [t][b][k]; out-projection as
// HMMA GEMM over the fp16 history (fp32 g_h buffer deleted).
// ---------------------------------------------------------------------------

namespace {
constexpr int Bn = 64;
constexpr int Sn = 512;
constexpr int In = 128;
constexpr int Hn = 2048;
constexpr int On = 128;
constexpr int KSPLIT = 9;
constexpr int NCTA = 144;             // 16 j-tiles x 9 k-slices
constexpr int NTHR = 512;             // 16 warps
constexpr int HB = Hn * Bn;
constexpr float kNoise = 0.005f;
constexpr float kAlpha = 0.2f;

// k16-units per slice: slices 0,1 get 15, slices 2..8 get 14 (2*15+7*14=128)
__host__ __device__ __forceinline__ int slice_units(int kq) { return 14 + (kq < 2); }
__host__ __device__ __forceinline__ int slice_start16(int kq) {
    return kq * 14 + (kq < 2 ? kq : 2);
}

// loop smem layout (bytes). Rows padded to 528B -> conflict-free ldmatrix.
constexpr int ROWB = 528;
constexpr int OFF_WH = 0;                       // 128*528 = 67584
constexpr int OFF_BH = OFF_WH + 128 * ROWB;     // 67584 (+64*528 = 33792)
constexpr int OFF_RED = OFF_BH;                 // pair-reduce stage overlay, 40960
constexpr int OFF_STG = OFF_RED + 40960;        // +16*66*4 = 4224
constexpr int SMEM_TOTAL = OFF_STG + 4224;      // 112768

// out-kernel smem layout
constexpr int ORB = 272;                        // 128 halves + 16B pad
constexpr int OFF_OB = 64 * ORB;                // A: 64 rows; B: 128 rows
constexpr int OSMEM = OFF_OB + 128 * ORB;       // 52224
}

// device globals (allocation-free rule)
__device__ float g_U[(size_t)Sn * Hn * Bn];          // [t][j][b] (t>=1)
__device__ float g_part[(size_t)KSPLIT * Hn * Bn];   // [q][j][b]
__device__ __half g_Wh[(size_t)Hn * Hn];             // [j][k] fp16 of 0.2*g[k]*wrec[j][k]
__device__ __half g_hb[(size_t)Bn * Hn];             // [b][k] fp16 h_{t-1}
__device__ __half g_hist[(size_t)Sn * Bn * Hn];      // [t][b][k] fp16 h history
__device__ __half g_woT[(size_t)On * Hn];            // [o][k] fp16 wout^T
__device__ unsigned g_bar_count;
__device__ unsigned g_bar_gen;

// ---- helpers ----
__device__ __forceinline__ uint32_t smem_u32(const void* p) {
    uint32_t a;
    asm("{ .reg .u64 t; cvta.to.shared.u64 t, %1; cvt.u32.u64 %0, t; }" : "=r"(a) : "l"(p));
    return a;
}
__device__ __forceinline__ void ldsm4(uint32_t a[4], uint32_t addr) {
    asm volatile("ldmatrix.sync.aligned.m8n8.x4.shared.b16 {%0,%1,%2,%3}, [%4];"
                 : "=r"(a[0]), "=r"(a[1]), "=r"(a[2]), "=r"(a[3]) : "r"(addr));
}
__device__ __forceinline__ void mma16816(float c[4], const uint32_t a[4],
                                         uint32_t b0, uint32_t b1) {
    asm volatile("mma.sync.aligned.m16n8k16.row.col.f32.f16.f16.f32 "
                 "{%0,%1,%2,%3}, {%4,%5,%6,%7}, {%8,%9}, {%0,%1,%2,%3};"
                 : "+f"(c[0]), "+f"(c[1]), "+f"(c[2]), "+f"(c[3])
                 : "r"(a[0]), "r"(a[1]), "r"(a[2]), "r"(a[3]), "r"(b0), "r"(b1));
}
__device__ __forceinline__ void ffma2(unsigned long long &acc, unsigned long long a,
                                      unsigned long long b) {
    asm("fma.rn.f32x2 %0, %1, %2, %0;" : "+l"(acc) : "l"(a), "l"(b));
}
__device__ __forceinline__ unsigned long long splat2(float w) {
    unsigned long long r;
    asm("mov.b64 %0, {%1, %1};" : "=l"(r) : "f"(w));
    return r;
}
__device__ __forceinline__ float2 unpack2(unsigned long long v) {
    float2 r;
    asm("mov.b64 {%0, %1}, %2;" : "=f"(r.x), "=f"(r.y) : "l"(v));
    return r;
}

// global grid barrier (replay-deterministic) -- proven, unchanged
__device__ __forceinline__ void grid_sync_dev() {
    __syncthreads();
    if (threadIdx.x == 0) {
        __threadfence();
        unsigned old, my;
        asm volatile("ld.acquire.gpu.global.u32 %0, [%1];"
                     : "=r"(old) : "l"(&g_bar_gen) : "memory");
        asm volatile("atom.release.gpu.global.add.u32 %0, [%1], %2;"
                     : "=r"(my) : "l"(&g_bar_count), "r"(1u) : "memory");
        if (my == (unsigned)(NCTA - 1)) {
            asm volatile("st.global.u32 [%0], %1;" :: "l"(&g_bar_count), "r"(0u) : "memory");
            asm volatile("red.release.gpu.global.add.u32 [%0], %1;"
                         :: "l"(&g_bar_gen), "r"(1u) : "memory");
        } else {
            unsigned cur;
            do {
                asm volatile("ld.acquire.gpu.global.u32 %0, [%1];"
                             : "=r"(cur) : "l"(&g_bar_gen) : "memory");
            } while (cur == old);
        }
        __threadfence();
    }
    __syncthreads();
}

// ---------------------------------------------------------------------------
// prep kernels
// ---------------------------------------------------------------------------
__global__ void wprep_kernel(const float* __restrict__ wrec, const float* __restrict__ g) {
    int n = blockIdx.x * blockDim.x + threadIdx.x;      // < Hn*Hn  ([j][k])
    int k = n & (Hn - 1);
    g_Wh[n] = __float2half_rn(kAlpha * g[k] * wrec[n]);
}

__global__ void hbinit_kernel(const float* __restrict__ h0) {
    int n = blockIdx.x * blockDim.x + threadIdx.x;      // < Bn*Hn, [b][k]
    __half v = __float2half_rn(h0[n & (Hn - 1)]);
    g_hb[n] = v;
    g_hist[n] = v;                                      // t = 0 slice
}

__global__ __launch_bounds__(1024) void wtprep_kernel(const float* __restrict__ wout) {
    __shared__ float s[32][33];
    int tx = threadIdx.x, ty = threadIdx.y;
    int k0 = blockIdx.x * 32, o0 = blockIdx.y * 32;
    s[ty][tx] = wout[(size_t)(k0 + ty) * On + o0 + tx];
    __syncthreads();
    g_woT[(size_t)(o0 + ty) * Hn + k0 + tx] = __float2half_rn(s[tx][ty]);
}

// ---------------------------------------------------------------------------
// U[t][j][b] = alpha * x[b][t-1]@wi[:,j] + noise_std*noise[b][t-1][j]
// ---------------------------------------------------------------------------
__global__ __launch_bounds__(256) void u_kernel(const float* __restrict__ x,
                                                const float* __restrict__ noise,
                                                const float* __restrict__ wi) {
    __shared__ float As[64][66];
    __shared__ float Ws[64][64];
    int t = blockIdx.y + 1;
    int j0 = blockIdx.x * 64;
    int tid = threadIdx.x;
    int by = tid & 15, jx = tid >> 4;
    int b0 = by * 4;
    unsigned long long acc[4][2] = {};

    for (int i0 = 0; i0 < In; i0 += 64) {
        #pragma unroll
        for (int p = 0; p < 16; p++) {
            int f = tid + p * 256;
            int i = f & 63, b = f >> 6;
            As[i][b] = x[((size_t)b * Sn + (t - 1)) * In + i0 + i];
        }
        #pragma unroll
        for (int p = 0; p < 4; p++) {
            int f = tid + p * 256;
            int i = f >> 4, c = f & 15;
            *(float4*)&Ws[i][c * 4] = *(const float4*)&wi[(size_t)(i0 + i) * Hn + j0 + c * 4];
        }
        __syncthreads();
        #pragma unroll 16
        for (int k = 0; k < 64; k++) {
            const unsigned long long* ap = (const unsigned long long*)&As[k][b0];
            unsigned long long a01 = ap[0], a23 = ap[1];
            float4 w = *(const float4*)&Ws[k][jx * 4];
            unsigned long long w0 = splat2(w.x), w1 = splat2(w.y),
                               w2 = splat2(w.z), w3 = splat2(w.w);
            ffma2(acc[0][0], a01, w0); ffma2(acc[0][1], a23, w0);
            ffma2(acc[1][0], a01, w1); ffma2(acc[1][1], a23, w1);
            ffma2(acc[2][0], a01, w2); ffma2(acc[2][1], a23, w2);
            ffma2(acc[3][0], a01, w3); ffma2(acc[3][1], a23, w3);
        }
        __syncthreads();
    }
    #pragma unroll
    for (int jj = 0; jj < 4; jj++) {
        int j = j0 + jx * 4 + jj;
        float2 lo = unpack2(acc[jj][0]), hi = unpack2(acc[jj][1]);
        float4 v;
        v.x = kAlpha * lo.x + kNoise * noise[((size_t)(b0 + 0) * Sn + (t - 1)) * Hn + j];
        v.y = kAlpha * lo.y + kNoise * noise[((size_t)(b0 + 1) * Sn + (t - 1)) * Hn + j];
        v.z = kAlpha * hi.x + kNoise * noise[((size_t)(b0 + 2) * Sn + (t - 1)) * Hn + j];
        v.w = kAlpha * hi.y + kNoise * noise[((size_t)(b0 + 3) * Sn + (t - 1)) * Hn + j];
        *(float4*)&g_U[((size_t)t * Hn + j) * Bn + b0] = v;
    }
}

// ---------------------------------------------------------------------------
// persistent HMMA loop (R8 structure). CTA (jt,kq): partial D[128j x 64b]
// over its k-slice (14/15 k16-units). Phase 2: CTAs 0..127 own 16 j each,
// h carried in registers; writes fp16 h to g_hb (next B) and g_hist[t].
// ---------------------------------------------------------------------------
__global__ __launch_bounds__(NTHR, 1) void loop_kernel(const float* __restrict__ h0) {
    extern __shared__ char smem[];
    const uint32_t sb = smem_u32(smem);
    const int tid = threadIdx.x;
    const int wid = tid >> 5, lane = tid & 31;
    const int cta = blockIdx.x;
    const int jt = cta / KSPLIT, kq = cta % KSPLIT;
    const int j0 = jt * 128;
    const int ku = slice_units(kq);           // 14 or 15
    const int ku2 = ku * 2;                   // 16B chunks per row
    const int kbase = slice_start16(kq) * 16; // element base
    const int u0 = (ku + 1) >> 1;             // khalf0 units (7 or 8)
    const int rc = cta * 16;                  // phase-2 j-base (cta < 128 only)

    const int tile = wid >> 1;                // 0..7
    const int khalf = wid & 1;
    const int mg = tile >> 1;                 // 0..3 (32 j each)
    const int nh = tile & 1;                  // 0..1 (32 b each)
    const int myU = khalf ? (ku - u0) : u0;   // k16-units for this warp
    const uint32_t koff = (uint32_t)(khalf ? u0 * 32 : 0);

    // phase-2 ownership (fixed forever): j = rc + jl, b = bb..bb+1
    const int jl = (tid * 2) >> 6;            // 0..15
    const int bb = (tid * 2) & 63;
    const size_t ownIdx = (size_t)(rc + jl) * Bn + bb;
    float2 hreg = make_float2(0.f, 0.f);
    if (cta < 128) { float v = h0[rc + jl]; hreg = make_float2(v, v); }

    // ---- prologue: resident W -> SMEM (padded rows) ----
    for (int p = 0; p < 8; p++) {
        int f = tid + p * 512;                // < 4096
        int r = f >> 5, c = f & 31;
        if (c < ku2)
            *(uint4*)(smem + OFF_WH + r * ROWB + c * 16) =
                *(const uint4*)&g_Wh[(size_t)(j0 + r) * Hn + kbase + c * 8];
    }
    __syncthreads();

    // per-lane ldmatrix addresses (byte offsets within W/B blocks)
    const uint32_t aLane =
        (uint32_t)(mg * 32 + (lane & 15)) * ROWB + koff + (lane >> 4) * 16;
    const uint32_t bLane =
        (uint32_t)(nh * 32 + (lane & 7) + ((lane >> 4) & 1) * 8) * ROWB +
        koff + ((lane >> 3) & 1) * 16;
    const int g8 = lane >> 2, tg = lane & 3;
    float* red = (float*)(smem + OFF_RED) + tile * 1280;   // 32 rows x 40 floats
    float (*stage)[66] = (float (*)[66])(smem + OFF_STG);

    for (int t = 1; t < Sn; t++) {
        // ---- load B (fp16 h slice) ----
        #pragma unroll
        for (int p = 0; p < 4; p++) {
            int f = tid + p * 512;            // < 2048
            int b = f >> 5, c = f & 31;
            if (c < ku2)
                *(uint4*)(smem + OFF_BH + b * ROWB + c * 16) =
                    __ldcg((const uint4*)&g_hb[(size_t)b * Hn + kbase + c * 8]);
        }
        __syncthreads();

        // ---- single mma chain ----
        float acc1[2][4][4] = {};
        {
            const uint32_t aHi = sb + OFF_WH + aLane;
            const uint32_t bBase = sb + OFF_BH + bLane;
            #pragma unroll 4
            for (int kk = 0; kk < myU; kk++) {
                uint32_t Bv[4], Bw[4], A0[4], A1[4];
                ldsm4(Bv, bBase + kk * 32);
                ldsm4(Bw, bBase + kk * 32 + 16 * ROWB);
                ldsm4(A0, aHi + kk * 32);
                ldsm4(A1, aHi + kk * 32 + 16 * ROWB);
                mma16816(acc1[0][0], A0, Bv[0], Bv[1]);
                mma16816(acc1[0][1], A0, Bv[2], Bv[3]);
                mma16816(acc1[0][2], A0, Bw[0], Bw[1]);
                mma16816(acc1[0][3], A0, Bw[2], Bw[3]);
                mma16816(acc1[1][0], A1, Bv[0], Bv[1]);
                mma16816(acc1[1][1], A1, Bv[2], Bv[3]);
                mma16816(acc1[1][2], A1, Bw[0], Bw[1]);
                mma16816(acc1[1][3], A1, Bw[2], Bw[3]);
            }
        }
        __syncthreads();   // all warps done reading B (red overlays BH)

        // ---- pair-reduce k halves, write g_part ----
        if (khalf) {
            #pragma unroll
            for (int mt = 0; mt < 2; mt++)
                #pragma unroll
                for (int nt = 0; nt < 4; nt++) {
                    int r0 = mt * 16 + g8, cc = nt * 8 + tg * 2;
                    *(float2*)&red[r0 * 40 + cc] =
                        make_float2(acc1[mt][nt][0], acc1[mt][nt][1]);
                    *(float2*)&red[(r0 + 8) * 40 + cc] =
                        make_float2(acc1[mt][nt][2], acc1[mt][nt][3]);
                }
        }
        __syncthreads();
        if (!khalf) {
            #pragma unroll
            for (int mt = 0; mt < 2; mt++)
                #pragma unroll
                for (int nt = 0; nt < 4; nt++) {
                    int r0 = mt * 16 + g8, cc = nt * 8 + tg * 2;
                    float2 p0 = *(float2*)&red[r0 * 40 + cc];
                    float2 p1 = *(float2*)&red[(r0 + 8) * 40 + cc];
                    int j = j0 + mg * 32 + r0;
                    int bc = nh * 32 + cc;
                    __stcg((float2*)&g_part[((size_t)kq * Hn + j) * Bn + bc],
                           make_float2(acc1[mt][nt][0] + p0.x, acc1[mt][nt][1] + p0.y));
                    __stcg((float2*)&g_part[((size_t)kq * Hn + j + 8) * Bn + bc],
                           make_float2(acc1[mt][nt][2] + p1.x, acc1[mt][nt][3] + p1.y));
                }
        }

        // ---- prefetch phase-2 U (barrier-independent) ----
        float2 uu = make_float2(0.f, 0.f);
        if (cta < 128) uu = *(const float2*)&g_U[(size_t)t * HB + ownIdx];

        grid_sync_dev();

        // ---- phase 2: reduce 9 k-slices + leak + U; CTAs 0..127 own 16 j each ----
        if (cta < 128) {
            float2 s = make_float2(0.f, 0.f);
            #pragma unroll
            for (int q = 0; q < KSPLIT; q++) {
                float2 v = __ldcg((const float2*)&g_part[(size_t)q * HB + ownIdx]);
                s.x += v.x; s.y += v.y;
            }
            hreg = make_float2((1.f - kAlpha) * hreg.x + s.x + uu.x,
                               (1.f - kAlpha) * hreg.y + s.y + uu.y);
            *(float2*)&stage[jl][bb] = hreg;
            __syncthreads();
            int b = tid >> 3, kk = tid & 7;
            __half2 hv;
            hv.x = __float2half_rn(stage[kk * 2][b]);
            hv.y = __float2half_rn(stage[kk * 2 + 1][b]);
            size_t off = (size_t)b * Hn + rc + kk * 2;
            *(__half2*)&g_hb[off] = hv;
            *(__half2*)&g_hist[(size_t)t * HB + off] = hv;
        }

        grid_sync_dev();
    }
}

// ---------------------------------------------------------------------------
// out[b][t][o] = sum_k g_hist[t][b][k] * woT[o][k]   (fp16 HMMA, one CTA per t)
// 8 warps: mg = wid>>2 (2 x 32 b), nh = wid&3 (4 x 32 o); K chunked by 128.
// ---------------------------------------------------------------------------
__global__ __launch_bounds__(256) void out_kernel(float* __restrict__ out) {
    extern __shared__ char sm[];
    const uint32_t sb = smem_u32(sm);
    const int t = blockIdx.x, tid = threadIdx.x;
    const int wid = tid >> 5, lane = tid & 31;
    const int mg = wid >> 2, nh = wid & 3;

    const uint32_t aLane = (uint32_t)(mg * 32 + (lane & 15)) * ORB + (lane >> 4) * 16;
    const uint32_t bLane =
        (uint32_t)(nh * 32 + (lane & 7) + ((lane >> 4) & 1) * 8) * ORB +
        ((lane >> 3) & 1) * 16;
    const int g8 = lane >> 2, tg = lane & 3;

    float acc[2][4][4] = {};
    const __half* hsrc = g_hist + (size_t)t * HB;

    for (int k0 = 0; k0 < Hn; k0 += 128) {
        #pragma unroll
        for (int p = 0; p < 4; p++) {
            int f = tid + p * 256;            // < 1024: A 64 rows x 16 chunks
            int r = f >> 4, c = f & 15;
            *(uint4*)(sm + r * ORB + c * 16) =
                *(const uint4*)&hsrc[(size_t)r * Hn + k0 + c * 8];
        }
        #pragma unroll
        for (int p = 0; p < 8; p++) {
            int f = tid + p * 256;            // < 2048: B 128 rows x 16 chunks
            int r = f >> 4, c = f & 15;
            *(uint4*)(sm + OFF_OB + r * ORB + c * 16) =
                *(const uint4*)&g_woT[(size_t)r * Hn + k0 + c * 8];
        }
        __syncthreads();
        const uint32_t aB = sb + aLane, bB = sb + OFF_OB + bLane;
        #pragma unroll
        for (int kk = 0; kk < 8; kk++) {
            uint32_t A0[4], A1[4], Bv[4], Bw[4];
            ldsm4(A0, aB + kk * 32);
            ldsm4(A1, aB + kk * 32 + 16 * ORB);
            ldsm4(Bv, bB + kk * 32);
            ldsm4(Bw, bB + kk * 32 + 16 * ORB);
            mma16816(acc[0][0], A0, Bv[0], Bv[1]);
            mma16816(acc[0][1], A0, Bv[2], Bv[3]);
            mma16816(acc[0][2], A0, Bw[0], Bw[1]);
            mma16816(acc[0][3], A0, Bw[2], Bw[3]);
            mma16816(acc[1][0], A1, Bv[0], Bv[1]);
            mma16816(acc[1][1], A1, Bv[2], Bv[3]);
            mma16816(acc[1][2], A1, Bw[0], Bw[1]);
            mma16816(acc[1][3], A1, Bw[2], Bw[3]);
        }
        __syncthreads();
    }

    #pragma unroll
    for (int mt = 0; mt < 2; mt++)
        #pragma unroll
        for (int nt = 0; nt < 4; nt++) {
            int r0 = mt * 16 + g8, cc = nt * 8 + tg * 2;
            int b = mg * 32 + r0;
            int o = nh * 32 + cc;
            *(float2*)&out[((size_t)b * Sn + t) * On + o] =
                make_float2(acc[mt][nt][0], acc[mt][nt][1]);
            *(float2*)&out[((size_t)(b + 8) * Sn + t) * On + o] =
                make_float2(acc[mt][nt][2], acc[mt][nt][3]);
        }
}

// ---------------------------------------------------------------------------
extern "C" void kernel_launch(void* const* d_in, const int* in_sizes, int n_in,
                              void* d_out, int out_size) {
    const float* x     = (const float*)d_in[0];
    const float* noise = (const float*)d_in[1];
    const float* wi    = (const float*)d_in[2];
    const float* wrec  = (const float*)d_in[3];
    const float* wout  = (const float*)d_in[4];
    const float* g     = (const float*)d_in[5];
    const float* h0    = (const float*)d_in[6];
    float* out = (float*)d_out;

    cudaFuncSetAttribute(loop_kernel, cudaFuncAttributeMaxDynamicSharedMemorySize,
                         SMEM_TOTAL);
    cudaFuncSetAttribute(out_kernel, cudaFuncAttributeMaxDynamicSharedMemorySize,
                         OSMEM);

    wprep_kernel<<<Hn * Hn / 256, 256>>>(wrec, g);
    wtprep_kernel<<<dim3(Hn / 32, On / 32), dim3(32, 32)>>>(wout);
    u_kernel<<<dim3(Hn / 64, Sn - 1), 256>>>(x, noise, wi);
    hbinit_kernel<<<HB / 256, 256>>>(h0);
    loop_kernel<<<NCTA, NTHR, SMEM_TOTAL>>>(h0);
    out_kernel<<<Sn, 256, OSMEM>>>(out);
}

// round 11
// speedup vs baseline: 1.2068x; 1.0860x over previous
#include <cuda_runtime.h>
#include <cuda_fp16.h>
#include <cstdint>
#include <cstddef>

// ---------------------------------------------------------------------------
// RNN_fish, persistent HMMA kernel, single fp16 chain:
//   h_t = 0.8*h_{t-1} + (g.h_{t-1}) @ (0.2*wrec^T) + U_t
// R11: loop warps retiled 8x2 (16j x 32b, full k-slice per warp) -> no
// pair-reduce stage; u_kernel converted to HMMA (x fp16, wiT hi+lo chains).
// ---------------------------------------------------------------------------

namespace {
constexpr int Bn = 64;
constexpr int Sn = 512;
constexpr int In = 128;
constexpr int Hn = 2048;
constexpr int On = 128;
constexpr int KSPLIT = 9;
constexpr int NCTA = 144;             // 16 j-tiles x 9 k-slices
constexpr int NTHR = 512;             // 16 warps
constexpr int HB = Hn * Bn;
constexpr float kNoise = 0.005f;
constexpr float kAlpha = 0.2f;
constexpr float kLoInv = 1.0f / 4096.0f;

// k16-units per slice: slices 0,1 get 15, slices 2..8 get 14 (2*15+7*14=128)
__host__ __device__ __forceinline__ int slice_units(int kq) { return 14 + (kq < 2); }
__host__ __device__ __forceinline__ int slice_start16(int kq) {
    return kq * 14 + (kq < 2 ? kq : 2);
}

// loop smem layout (bytes). Rows padded to 528B -> conflict-free ldmatrix.
constexpr int ROWB = 528;
constexpr int OFF_WH = 0;                       // 128*528 = 67584
constexpr int OFF_BH = OFF_WH + 128 * ROWB;     // 67584 (+64*528 = 33792)
constexpr int OFF_STG = OFF_BH;                 // phase-2 stage overlays B
constexpr int SMEM_TOTAL = OFF_BH + 64 * ROWB;  // 101376

// u-kernel smem layout
constexpr int UROWB = 272;                      // 128 halves + 16B pad
constexpr int UOFF_BH = 64 * UROWB;             // A: 64 rows -> 17408
constexpr int UOFF_BL = UOFF_BH + 128 * UROWB;  // 52224
constexpr int USMEM = UOFF_BL + 128 * UROWB;    // 87040 (stage overlays A+Bhi)

// out-kernel smem layout
constexpr int ORB = 272;
constexpr int OFF_OB = 64 * ORB;
constexpr int OSMEM = OFF_OB + 128 * ORB;       // 52224
}

// device globals (allocation-free rule)
__device__ float g_U[(size_t)Sn * Hn * Bn];          // [t][j][b] (t>=1)
__device__ float g_part[(size_t)KSPLIT * Hn * Bn];   // [q][j][b]
__device__ __half g_Wh[(size_t)Hn * Hn];             // [j][k] fp16 of 0.2*g[k]*wrec[j][k]
__device__ __half g_hb[(size_t)Bn * Hn];             // [b][k] fp16 h_{t-1}
__device__ __half g_hist[(size_t)Sn * Bn * Hn];      // [t][b][k] fp16 h history
__device__ __half g_woT[(size_t)On * Hn];            // [o][k] fp16 wout^T
__device__ __half g_wiTh[(size_t)Hn * In];           // [j][i] fp16 hi of wi^T
__device__ __half g_wiTl[(size_t)Hn * In];           // [j][i] fp16 4096*lo
__device__ __half g_xh[(size_t)Bn * Sn * In];        // [b][t][i] fp16 x
__device__ unsigned g_bar_count;
__device__ unsigned g_bar_gen;

// ---- helpers ----
__device__ __forceinline__ uint32_t smem_u32(const void* p) {
    uint32_t a;
    asm("{ .reg .u64 t; cvta.to.shared.u64 t, %1; cvt.u32.u64 %0, t; }" : "=r"(a) : "l"(p));
    return a;
}
__device__ __forceinline__ void ldsm4(uint32_t a[4], uint32_t addr) {
    asm volatile("ldmatrix.sync.aligned.m8n8.x4.shared.b16 {%0,%1,%2,%3}, [%4];"
                 : "=r"(a[0]), "=r"(a[1]), "=r"(a[2]), "=r"(a[3]) : "r"(addr));
}
__device__ __forceinline__ void mma16816(float c[4], const uint32_t a[4],
                                         uint32_t b0, uint32_t b1) {
    asm volatile("mma.sync.aligned.m16n8k16.row.col.f32.f16.f16.f32 "
                 "{%0,%1,%2,%3}, {%4,%5,%6,%7}, {%8,%9}, {%0,%1,%2,%3};"
                 : "+f"(c[0]), "+f"(c[1]), "+f"(c[2]), "+f"(c[3])
                 : "r"(a[0]), "r"(a[1]), "r"(a[2]), "r"(a[3]), "r"(b0), "r"(b1));
}

// global grid barrier (replay-deterministic) -- proven, unchanged
__device__ __forceinline__ void grid_sync_dev() {
    __syncthreads();
    if (threadIdx.x == 0) {
        __threadfence();
        unsigned old, my;
        asm volatile("ld.acquire.gpu.global.u32 %0, [%1];"
                     : "=r"(old) : "l"(&g_bar_gen) : "memory");
        asm volatile("atom.release.gpu.global.add.u32 %0, [%1], %2;"
                     : "=r"(my) : "l"(&g_bar_count), "r"(1u) : "memory");
        if (my == (unsigned)(NCTA - 1)) {
            asm volatile("st.global.u32 [%0], %1;" :: "l"(&g_bar_count), "r"(0u) : "memory");
            asm volatile("red.release.gpu.global.add.u32 [%0], %1;"
                         :: "l"(&g_bar_gen), "r"(1u) : "memory");
        } else {
            unsigned cur;
            do {
                asm volatile("ld.acquire.gpu.global.u32 %0, [%1];"
                             : "=r"(cur) : "l"(&g_bar_gen) : "memory");
            } while (cur == old);
        }
        __threadfence();
    }
    __syncthreads();
}

// ---------------------------------------------------------------------------
// prep kernels
// ---------------------------------------------------------------------------
__global__ void wprep_kernel(const float* __restrict__ wrec, const float* __restrict__ g) {
    int n = blockIdx.x * blockDim.x + threadIdx.x;      // < Hn*Hn  ([j][k])
    int k = n & (Hn - 1);
    g_Wh[n] = __float2half_rn(kAlpha * g[k] * wrec[n]);
}

__global__ void hbinit_kernel(const float* __restrict__ h0) {
    int n = blockIdx.x * blockDim.x + threadIdx.x;      // < Bn*Hn, [b][k]
    __half v = __float2half_rn(h0[n & (Hn - 1)]);
    g_hb[n] = v;
    g_hist[n] = v;                                      // t = 0 slice
}

__global__ void xhprep_kernel(const float* __restrict__ x) {
    int n = blockIdx.x * blockDim.x + threadIdx.x;      // < Bn*Sn*In
    g_xh[n] = __float2half_rn(x[n]);
}

__global__ __launch_bounds__(1024) void wtprep_kernel(const float* __restrict__ wout) {
    __shared__ float s[32][33];
    int tx = threadIdx.x, ty = threadIdx.y;
    int k0 = blockIdx.x * 32, o0 = blockIdx.y * 32;
    s[ty][tx] = wout[(size_t)(k0 + ty) * On + o0 + tx];
    __syncthreads();
    g_woT[(size_t)(o0 + ty) * Hn + k0 + tx] = __float2half_rn(s[tx][ty]);
}

__global__ __launch_bounds__(1024) void witprep_kernel(const float* __restrict__ wi) {
    __shared__ float s[32][33];
    int tx = threadIdx.x, ty = threadIdx.y;
    int i0 = blockIdx.x * 32, j0 = blockIdx.y * 32;
    s[ty][tx] = wi[(size_t)(i0 + ty) * Hn + j0 + tx];
    __syncthreads();
    float v = s[tx][ty];
    __half hi = __float2half_rn(v);
    g_wiTh[(size_t)(j0 + ty) * In + i0 + tx] = hi;
    g_wiTl[(size_t)(j0 + ty) * In + i0 + tx] =
        __float2half_rn((v - __half2float(hi)) * 4096.0f);
}

// ---------------------------------------------------------------------------
// u_kernel (HMMA): U[t][j][b] = alpha * x[b][t-1]@wi[:,j] + noise*n[b][t-1][j]
// CTA = (j-tile 128, t). D[b][j] via A = x rows (fp16), B = wiT hi + lo/4096.
// Epilogue transposes through SMEM -> g_U[t][j][b] (layout unchanged).
// ---------------------------------------------------------------------------
__global__ __launch_bounds__(256) void u_kernel(const float* __restrict__ noise) {
    extern __shared__ char sm[];
    const uint32_t sb = smem_u32(sm);
    const int jt = blockIdx.x, t = blockIdx.y + 1;
    const int j0 = jt * 128;
    const int tid = threadIdx.x;
    const int wid = tid >> 5, lane = tid & 31;
    const int mgb = wid >> 2;            // 0..1: 32 b each
    const int njw = wid & 3;             // 0..3: 32 j each
    const int g8 = lane >> 2, tg = lane & 3;

    // load A (x tile: 64 b x 128 i)
    #pragma unroll
    for (int p = 0; p < 4; p++) {
        int f = tid + p * 256;           // < 1024
        int r = f >> 4, c = f & 15;
        *(uint4*)(sm + r * UROWB + c * 16) =
            *(const uint4*)&g_xh[((size_t)r * Sn + (t - 1)) * In + c * 8];
    }
    // load B (wiT hi/lo: 128 j x 128 i)
    #pragma unroll
    for (int p = 0; p < 8; p++) {
        int f = tid + p * 256;           // < 2048
        int r = f >> 4, c = f & 15;
        size_t gi = (size_t)(j0 + r) * In + c * 8;
        *(uint4*)(sm + UOFF_BH + r * UROWB + c * 16) = *(const uint4*)&g_wiTh[gi];
        *(uint4*)(sm + UOFF_BL + r * UROWB + c * 16) = *(const uint4*)&g_wiTl[gi];
    }
    __syncthreads();

    const uint32_t aLane =
        sb + (uint32_t)(mgb * 32 + (lane & 15)) * UROWB + (lane >> 4) * 16;
    const uint32_t bLane =
        (uint32_t)(njw * 32 + (lane & 7) + ((lane >> 4) & 1) * 8) * UROWB +
        ((lane >> 3) & 1) * 16;

    float a1[2][4][4] = {}, a2[2][4][4] = {};
    #pragma unroll
    for (int kk = 0; kk < 8; kk++) {
        uint32_t A0[4], A1[4], Bv[4], Bw[4];
        ldsm4(A0, aLane + kk * 32);
        ldsm4(A1, aLane + kk * 32 + 16 * UROWB);
        ldsm4(Bv, sb + UOFF_BH + bLane + kk * 32);
        ldsm4(Bw, sb + UOFF_BH + bLane + kk * 32 + 16 * UROWB);
        mma16816(a1[0][0], A0, Bv[0], Bv[1]); mma16816(a1[0][1], A0, Bv[2], Bv[3]);
        mma16816(a1[0][2], A0, Bw[0], Bw[1]); mma16816(a1[0][3], A0, Bw[2], Bw[3]);
        mma16816(a1[1][0], A1, Bv[0], Bv[1]); mma16816(a1[1][1], A1, Bv[2], Bv[3]);
        mma16816(a1[1][2], A1, Bw[0], Bw[1]); mma16816(a1[1][3], A1, Bw[2], Bw[3]);
        ldsm4(Bv, sb + UOFF_BL + bLane + kk * 32);
        ldsm4(Bw, sb + UOFF_BL + bLane + kk * 32 + 16 * UROWB);
        mma16816(a2[0][0], A0, Bv[0], Bv[1]); mma16816(a2[0][1], A0, Bv[2], Bv[3]);
        mma16816(a2[0][2], A0, Bw[0], Bw[1]); mma16816(a2[0][3], A0, Bw[2], Bw[3]);
        mma16816(a2[1][0], A1, Bv[0], Bv[1]); mma16816(a2[1][1], A1, Bv[2], Bv[3]);
        mma16816(a2[1][2], A1, Bw[0], Bw[1]); mma16816(a2[1][3], A1, Bw[2], Bw[3]);
    }
    __syncthreads();                     // done reading A/B; stage overlays them

    float (*stage)[132] = (float (*)[132])sm;   // [b 64][j 128]
    #pragma unroll
    for (int mt = 0; mt < 2; mt++)
        #pragma unroll
        for (int nt = 0; nt < 4; nt++) {
            int rb = mgb * 32 + mt * 16 + g8;
            int jc = njw * 32 + nt * 8 + tg * 2;
            stage[rb][jc]     = fmaf(kLoInv, a2[mt][nt][0], a1[mt][nt][0]);
            stage[rb][jc + 1] = fmaf(kLoInv, a2[mt][nt][1], a1[mt][nt][1]);
            stage[rb + 8][jc]     = fmaf(kLoInv, a2[mt][nt][2], a1[mt][nt][2]);
            stage[rb + 8][jc + 1] = fmaf(kLoInv, a2[mt][nt][3], a1[mt][nt][3]);
        }
    __syncthreads();

    // noise phase: coalesced in j
    #pragma unroll
    for (int rep = 0; rep < 8; rep++) {
        int b = wid * 8 + rep;
        #pragma unroll
        for (int c = 0; c < 4; c++) {
            int j = c * 32 + lane;
            float nv = noise[((size_t)b * Sn + (t - 1)) * Hn + j0 + j];
            stage[b][j] = fmaf(kAlpha, stage[b][j], kNoise * nv);
        }
    }
    __syncthreads();

    // store phase: coalesced in b
    {
        int j = tid >> 1, bh = (tid & 1) * 32;
        #pragma unroll
        for (int bc = 0; bc < 8; bc++) {
            int b0 = bh + bc * 4;
            float4 v = make_float4(stage[b0][j], stage[b0 + 1][j],
                                   stage[b0 + 2][j], stage[b0 + 3][j]);
            *(float4*)&g_U[((size_t)t * Hn + j0 + j) * Bn + b0] = v;
        }
    }
}

// ---------------------------------------------------------------------------
// persistent HMMA loop. CTA (jt,kq): partial D[128j x 64b] over its k-slice.
// 16 warps: mg = wid>>1 (8 x 16j), nh = wid&1 (2 x 32b); each warp full
// k-slice -> disjoint outputs, no pair-reduce. Phase 2 unchanged from R10.
// ---------------------------------------------------------------------------
__global__ __launch_bounds__(NTHR, 1) void loop_kernel(const float* __restrict__ h0) {
    extern __shared__ char smem[];
    const uint32_t sb = smem_u32(smem);
    const int tid = threadIdx.x;
    const int wid = tid >> 5, lane = tid & 31;
    const int cta = blockIdx.x;
    const int jt = cta / KSPLIT, kq = cta % KSPLIT;
    const int j0 = jt * 128;
    const int ku = slice_units(kq);           // 14 or 15
    const int ku2 = ku * 2;                   // 16B chunks per row
    const int kbase = slice_start16(kq) * 16; // element base
    const int rc = cta * 16;                  // phase-2 j-base (cta < 128 only)

    const int mg = wid >> 1;                  // 0..7 (16 j each)
    const int nh = wid & 1;                   // 0..1 (32 b each)
    const int g8 = lane >> 2, tg = lane & 3;

    // phase-2 ownership (fixed forever): j = rc + jl, b = bb..bb+1
    const int jl = (tid * 2) >> 6;            // 0..15
    const int bb = (tid * 2) & 63;
    const size_t ownIdx = (size_t)(rc + jl) * Bn + bb;
    float2 hreg = make_float2(0.f, 0.f);
    if (cta < 128) { float v = h0[rc + jl]; hreg = make_float2(v, v); }

    // ---- prologue: resident W -> SMEM (padded rows) ----
    for (int p = 0; p < 8; p++) {
        int f = tid + p * 512;                // < 4096
        int r = f >> 5, c = f & 31;
        if (c < ku2)
            *(uint4*)(smem + OFF_WH + r * ROWB + c * 16) =
                *(const uint4*)&g_Wh[(size_t)(j0 + r) * Hn + kbase + c * 8];
    }
    __syncthreads();

    const uint32_t aLane =
        sb + OFF_WH + (uint32_t)(mg * 16 + (lane & 15)) * ROWB + (lane >> 4) * 16;
    const uint32_t bLane =
        sb + OFF_BH + (uint32_t)(nh * 32 + (lane & 7) + ((lane >> 4) & 1) * 8) * ROWB +
        ((lane >> 3) & 1) * 16;
    float (*stage)[66] = (float (*)[66])(smem + OFF_STG);

    for (int t = 1; t < Sn; t++) {
        // ---- load B (fp16 h slice) ----
        #pragma unroll
        for (int p = 0; p < 4; p++) {
            int f = tid + p * 512;            // < 2048
            int b = f >> 5, c = f & 31;
            if (c < ku2)
                *(uint4*)(smem + OFF_BH + b * ROWB + c * 16) =
                    __ldcg((const uint4*)&g_hb[(size_t)b * Hn + kbase + c * 8]);
        }
        __syncthreads();

        // ---- single mma chain, full k-slice per warp ----
        float acc[4][4] = {};
        #pragma unroll 5
        for (int kk = 0; kk < ku; kk++) {
            uint32_t A0[4], Bv[4], Bw[4];
            ldsm4(A0, aLane + kk * 32);
            ldsm4(Bv, bLane + kk * 32);
            ldsm4(Bw, bLane + kk * 32 + 16 * ROWB);
            mma16816(acc[0], A0, Bv[0], Bv[1]);
            mma16816(acc[1], A0, Bv[2], Bv[3]);
            mma16816(acc[2], A0, Bw[0], Bw[1]);
            mma16816(acc[3], A0, Bw[2], Bw[3]);
        }
        __syncthreads();                      // done reading B (stage overlays)

        // ---- direct store to g_part (disjoint per warp) ----
        #pragma unroll
        for (int nt = 0; nt < 4; nt++) {
            int j = j0 + mg * 16 + g8;
            int bc = nh * 32 + nt * 8 + tg * 2;
            __stcg((float2*)&g_part[((size_t)kq * Hn + j) * Bn + bc],
                   make_float2(acc[nt][0], acc[nt][1]));
            __stcg((float2*)&g_part[((size_t)kq * Hn + j + 8) * Bn + bc],
                   make_float2(acc[nt][2], acc[nt][3]));
        }

        // ---- prefetch phase-2 U (barrier-independent) ----
        float2 uu = make_float2(0.f, 0.f);
        if (cta < 128) uu = *(const float2*)&g_U[(size_t)t * HB + ownIdx];

        grid_sync_dev();

        // ---- phase 2: reduce 9 k-slices + leak + U; CTAs 0..127 own 16 j each ----
        if (cta < 128) {
            float2 s = make_float2(0.f, 0.f);
            #pragma unroll
            for (int q = 0; q < KSPLIT; q++) {
                float2 v = __ldcg((const float2*)&g_part[(size_t)q * HB + ownIdx]);
                s.x += v.x; s.y += v.y;
            }
            hreg = make_float2((1.f - kAlpha) * hreg.x + s.x + uu.x,
                               (1.f - kAlpha) * hreg.y + s.y + uu.y);
            *(float2*)&stage[jl][bb] = hreg;
            __syncthreads();
            int b = tid >> 3, kk = tid & 7;
            __half2 hv;
            hv.x = __float2half_rn(stage[kk * 2][b]);
            hv.y = __float2half_rn(stage[kk * 2 + 1][b]);
            size_t off = (size_t)b * Hn + rc + kk * 2;
            *(__half2*)&g_hb[off] = hv;
            *(__half2*)&g_hist[(size_t)t * HB + off] = hv;
        }

        grid_sync_dev();
    }
}

// ---------------------------------------------------------------------------
// out[b][t][o] = sum_k g_hist[t][b][k] * woT[o][k]   (fp16 HMMA, one CTA per t)
// ---------------------------------------------------------------------------
__global__ __launch_bounds__(256) void out_kernel(float* __restrict__ out) {
    extern __shared__ char sm[];
    const uint32_t sb = smem_u32(sm);
    const int t = blockIdx.x, tid = threadIdx.x;
    const int wid = tid >> 5, lane = tid & 31;
    const int mg = wid >> 2, nh = wid & 3;

    const uint32_t aLane = (uint32_t)(mg * 32 + (lane & 15)) * ORB + (lane >> 4) * 16;
    const uint32_t bLane =
        (uint32_t)(nh * 32 + (lane & 7) + ((lane >> 4) & 1) * 8) * ORB +
        ((lane >> 3) & 1) * 16;
    const int g8 = lane >> 2, tg = lane & 3;

    float acc[2][4][4] = {};
    const __half* hsrc = g_hist + (size_t)t * HB;

    for (int k0 = 0; k0 < Hn; k0 += 128) {
        #pragma unroll
        for (int p = 0; p < 4; p++) {
            int f = tid + p * 256;
            int r = f >> 4, c = f & 15;
            *(uint4*)(sm + r * ORB + c * 16) =
                *(const uint4*)&hsrc[(size_t)r * Hn + k0 + c * 8];
        }
        #pragma unroll
        for (int p = 0; p < 8; p++) {
            int f = tid + p * 256;
            int r = f >> 4, c = f & 15;
            *(uint4*)(sm + OFF_OB + r * ORB + c * 16) =
                *(const uint4*)&g_woT[(size_t)r * Hn + k0 + c * 8];
        }
        __syncthreads();
        const uint32_t aB = sb + aLane, bB = sb + OFF_OB + bLane;
        #pragma unroll
        for (int kk = 0; kk < 8; kk++) {
            uint32_t A0[4], A1[4], Bv[4], Bw[4];
            ldsm4(A0, aB + kk * 32);
            ldsm4(A1, aB + kk * 32 + 16 * ORB);
            ldsm4(Bv, bB + kk * 32);
            ldsm4(Bw, bB + kk * 32 + 16 * ORB);
            mma16816(acc[0][0], A0, Bv[0], Bv[1]);
            mma16816(acc[0][1], A0, Bv[2], Bv[3]);
            mma16816(acc[0][2], A0, Bw[0], Bw[1]);
            mma16816(acc[0][3], A0, Bw[2], Bw[3]);
            mma16816(acc[1][0], A1, Bv[0], Bv[1]);
            mma16816(acc[1][1], A1, Bv[2], Bv[3]);
            mma16816(acc[1][2], A1, Bw[0], Bw[1]);
            mma16816(acc[1][3], A1, Bw[2], Bw[3]);
        }
        __syncthreads();
    }

    #pragma unroll
    for (int mt = 0; mt < 2; mt++)
        #pragma unroll
        for (int nt = 0; nt < 4; nt++) {
            int r0 = mt * 16 + g8, cc = nt * 8 + tg * 2;
            int b = mg * 32 + r0;
            int o = nh * 32 + cc;
            *(float2*)&out[((size_t)b * Sn + t) * On + o] =
                make_float2(acc[mt][nt][0], acc[mt][nt][1]);
            *(float2*)&out[((size_t)(b + 8) * Sn + t) * On + o] =
                make_float2(acc[mt][nt][2], acc[mt][nt][3]);
        }
}

// ---------------------------------------------------------------------------
extern "C" void kernel_launch(void* const* d_in, const int* in_sizes, int n_in,
                              void* d_out, int out_size) {
    const float* x     = (const float*)d_in[0];
    const float* noise = (const float*)d_in[1];
    const float* wi    = (const float*)d_in[2];
    const float* wrec  = (const float*)d_in[3];
    const float* wout  = (const float*)d_in[4];
    const float* g     = (const float*)d_in[5];
    const float* h0    = (const float*)d_in[6];
    float* out = (float*)d_out;

    cudaFuncSetAttribute(loop_kernel, cudaFuncAttributeMaxDynamicSharedMemorySize,
                         SMEM_TOTAL);
    cudaFuncSetAttribute(u_kernel, cudaFuncAttributeMaxDynamicSharedMemorySize,
                         USMEM);
    cudaFuncSetAttribute(out_kernel, cudaFuncAttributeMaxDynamicSharedMemorySize,
                         OSMEM);

    wprep_kernel<<<Hn * Hn / 256, 256>>>(wrec, g);
    wtprep_kernel<<<dim3(Hn / 32, On / 32), dim3(32, 32)>>>(wout);
    witprep_kernel<<<dim3(In / 32, Hn / 32), dim3(32, 32)>>>(wi);
    xhprep_kernel<<<Bn * Sn * In / 256, 256>>>(x);
    hbinit_kernel<<<HB / 256, 256>>>(h0);
    u_kernel<<<dim3(Hn / 128, Sn - 1), 256, USMEM>>>(noise);
    loop_kernel<<<NCTA, NTHR, SMEM_TOTAL>>>(h0);
    out_kernel<<<Sn, 256, OSMEM>>>(out);
}

// round 12
// speedup vs baseline: 1.2533x; 1.0386x over previous
#include <cuda_runtime.h>
#include <cuda_fp16.h>
#include <cstdint>
#include <cstddef>

// ---------------------------------------------------------------------------
// RNN_fish, persistent HMMA kernel, single fp16 chain:
//   h_t = 0.8*h_{t-1} + (g.h_{t-1}) @ (0.2*wrec^T) + U_t
// R12: step GEMM retiled to 8 compute warps x (32j x 32b), full k-slice per
// warp -> SMEM fragment traffic ~237KB/step/CTA (was 369KB). Warps 8-15 do
// loads + phase-2 only. u/out kernels unchanged (HMMA).
// ---------------------------------------------------------------------------

namespace {
constexpr int Bn = 64;
constexpr int Sn = 512;
constexpr int In = 128;
constexpr int Hn = 2048;
constexpr int On = 128;
constexpr int KSPLIT = 9;
constexpr int NCTA = 144;             // 16 j-tiles x 9 k-slices
constexpr int NTHR = 512;             // 16 warps (8 compute)
constexpr int HB = Hn * Bn;
constexpr float kNoise = 0.005f;
constexpr float kAlpha = 0.2f;
constexpr float kLoInv = 1.0f / 4096.0f;

// k16-units per slice: slices 0,1 get 15, slices 2..8 get 14 (2*15+7*14=128)
__host__ __device__ __forceinline__ int slice_units(int kq) { return 14 + (kq < 2); }
__host__ __device__ __forceinline__ int slice_start16(int kq) {
    return kq * 14 + (kq < 2 ? kq : 2);
}

// loop smem layout (bytes). Rows padded to 528B -> conflict-free ldmatrix.
constexpr int ROWB = 528;
constexpr int OFF_WH = 0;                       // 128*528 = 67584
constexpr int OFF_BH = OFF_WH + 128 * ROWB;     // 67584 (+64*528 = 33792)
constexpr int OFF_STG = OFF_BH;                 // phase-2 stage overlays B
constexpr int SMEM_TOTAL = OFF_BH + 64 * ROWB;  // 101376

// u-kernel smem layout
constexpr int UROWB = 272;                      // 128 halves + 16B pad
constexpr int UOFF_BH = 64 * UROWB;             // A: 64 rows -> 17408
constexpr int UOFF_BL = UOFF_BH + 128 * UROWB;  // 52224
constexpr int USMEM = UOFF_BL + 128 * UROWB;    // 87040 (stage overlays A+Bhi)

// out-kernel smem layout
constexpr int ORB = 272;
constexpr int OFF_OB = 64 * ORB;
constexpr int OSMEM = OFF_OB + 128 * ORB;       // 52224
}

// device globals (allocation-free rule)
__device__ float g_U[(size_t)Sn * Hn * Bn];          // [t][j][b] (t>=1)
__device__ float g_part[(size_t)KSPLIT * Hn * Bn];   // [q][j][b]
__device__ __half g_Wh[(size_t)Hn * Hn];             // [j][k] fp16 of 0.2*g[k]*wrec[j][k]
__device__ __half g_hb[(size_t)Bn * Hn];             // [b][k] fp16 h_{t-1}
__device__ __half g_hist[(size_t)Sn * Bn * Hn];      // [t][b][k] fp16 h history
__device__ __half g_woT[(size_t)On * Hn];            // [o][k] fp16 wout^T
__device__ __half g_wiTh[(size_t)Hn * In];           // [j][i] fp16 hi of wi^T
__device__ __half g_wiTl[(size_t)Hn * In];           // [j][i] fp16 4096*lo
__device__ __half g_xh[(size_t)Bn * Sn * In];        // [b][t][i] fp16 x
__device__ unsigned g_bar_count;
__device__ unsigned g_bar_gen;

// ---- helpers ----
__device__ __forceinline__ uint32_t smem_u32(const void* p) {
    uint32_t a;
    asm("{ .reg .u64 t; cvta.to.shared.u64 t, %1; cvt.u32.u64 %0, t; }" : "=r"(a) : "l"(p));
    return a;
}
__device__ __forceinline__ void ldsm4(uint32_t a[4], uint32_t addr) {
    asm volatile("ldmatrix.sync.aligned.m8n8.x4.shared.b16 {%0,%1,%2,%3}, [%4];"
                 : "=r"(a[0]), "=r"(a[1]), "=r"(a[2]), "=r"(a[3]) : "r"(addr));
}
__device__ __forceinline__ void mma16816(float c[4], const uint32_t a[4],
                                         uint32_t b0, uint32_t b1) {
    asm volatile("mma.sync.aligned.m16n8k16.row.col.f32.f16.f16.f32 "
                 "{%0,%1,%2,%3}, {%4,%5,%6,%7}, {%8,%9}, {%0,%1,%2,%3};"
                 : "+f"(c[0]), "+f"(c[1]), "+f"(c[2]), "+f"(c[3])
                 : "r"(a[0]), "r"(a[1]), "r"(a[2]), "r"(a[3]), "r"(b0), "r"(b1));
}

// global grid barrier (replay-deterministic) -- proven, unchanged
__device__ __forceinline__ void grid_sync_dev() {
    __syncthreads();
    if (threadIdx.x == 0) {
        __threadfence();
        unsigned old, my;
        asm volatile("ld.acquire.gpu.global.u32 %0, [%1];"
                     : "=r"(old) : "l"(&g_bar_gen) : "memory");
        asm volatile("atom.release.gpu.global.add.u32 %0, [%1], %2;"
                     : "=r"(my) : "l"(&g_bar_count), "r"(1u) : "memory");
        if (my == (unsigned)(NCTA - 1)) {
            asm volatile("st.global.u32 [%0], %1;" :: "l"(&g_bar_count), "r"(0u) : "memory");
            asm volatile("red.release.gpu.global.add.u32 [%0], %1;"
                         :: "l"(&g_bar_gen), "r"(1u) : "memory");
        } else {
            unsigned cur;
            do {
                asm volatile("ld.acquire.gpu.global.u32 %0, [%1];"
                             : "=r"(cur) : "l"(&g_bar_gen) : "memory");
            } while (cur == old);
        }
        __threadfence();
    }
    __syncthreads();
}

// ---------------------------------------------------------------------------
// prep kernels
// ---------------------------------------------------------------------------
__global__ void wprep_kernel(const float* __restrict__ wrec, const float* __restrict__ g) {
    int n = blockIdx.x * blockDim.x + threadIdx.x;      // < Hn*Hn  ([j][k])
    int k = n & (Hn - 1);
    g_Wh[n] = __float2half_rn(kAlpha * g[k] * wrec[n]);
}

__global__ void hbinit_kernel(const float* __restrict__ h0) {
    int n = blockIdx.x * blockDim.x + threadIdx.x;      // < Bn*Hn, [b][k]
    __half v = __float2half_rn(h0[n & (Hn - 1)]);
    g_hb[n] = v;
    g_hist[n] = v;                                      // t = 0 slice
}

__global__ void xhprep_kernel(const float* __restrict__ x) {
    int n = blockIdx.x * blockDim.x + threadIdx.x;      // < Bn*Sn*In
    g_xh[n] = __float2half_rn(x[n]);
}

__global__ __launch_bounds__(1024) void wtprep_kernel(const float* __restrict__ wout) {
    __shared__ float s[32][33];
    int tx = threadIdx.x, ty = threadIdx.y;
    int k0 = blockIdx.x * 32, o0 = blockIdx.y * 32;
    s[ty][tx] = wout[(size_t)(k0 + ty) * On + o0 + tx];
    __syncthreads();
    g_woT[(size_t)(o0 + ty) * Hn + k0 + tx] = __float2half_rn(s[tx][ty]);
}

__global__ __launch_bounds__(1024) void witprep_kernel(const float* __restrict__ wi) {
    __shared__ float s[32][33];
    int tx = threadIdx.x, ty = threadIdx.y;
    int i0 = blockIdx.x * 32, j0 = blockIdx.y * 32;
    s[ty][tx] = wi[(size_t)(i0 + ty) * Hn + j0 + tx];
    __syncthreads();
    float v = s[tx][ty];
    __half hi = __float2half_rn(v);
    g_wiTh[(size_t)(j0 + ty) * In + i0 + tx] = hi;
    g_wiTl[(size_t)(j0 + ty) * In + i0 + tx] =
        __float2half_rn((v - __half2float(hi)) * 4096.0f);
}

// ---------------------------------------------------------------------------
// u_kernel (HMMA): U[t][j][b] = alpha * x[b][t-1]@wi[:,j] + noise*n[b][t-1][j]
// ---------------------------------------------------------------------------
__global__ __launch_bounds__(256) void u_kernel(const float* __restrict__ noise) {
    extern __shared__ char sm[];
    const uint32_t sb = smem_u32(sm);
    const int jt = blockIdx.x, t = blockIdx.y + 1;
    const int j0 = jt * 128;
    const int tid = threadIdx.x;
    const int wid = tid >> 5, lane = tid & 31;
    const int mgb = wid >> 2;            // 0..1: 32 b each
    const int njw = wid & 3;             // 0..3: 32 j each
    const int g8 = lane >> 2, tg = lane & 3;

    #pragma unroll
    for (int p = 0; p < 4; p++) {
        int f = tid + p * 256;           // < 1024
        int r = f >> 4, c = f & 15;
        *(uint4*)(sm + r * UROWB + c * 16) =
            *(const uint4*)&g_xh[((size_t)r * Sn + (t - 1)) * In + c * 8];
    }
    #pragma unroll
    for (int p = 0; p < 8; p++) {
        int f = tid + p * 256;           // < 2048
        int r = f >> 4, c = f & 15;
        size_t gi = (size_t)(j0 + r) * In + c * 8;
        *(uint4*)(sm + UOFF_BH + r * UROWB + c * 16) = *(const uint4*)&g_wiTh[gi];
        *(uint4*)(sm + UOFF_BL + r * UROWB + c * 16) = *(const uint4*)&g_wiTl[gi];
    }
    __syncthreads();

    const uint32_t aLane =
        sb + (uint32_t)(mgb * 32 + (lane & 15)) * UROWB + (lane >> 4) * 16;
    const uint32_t bLane =
        (uint32_t)(njw * 32 + (lane & 7) + ((lane >> 4) & 1) * 8) * UROWB +
        ((lane >> 3) & 1) * 16;

    float a1[2][4][4] = {}, a2[2][4][4] = {};
    #pragma unroll
    for (int kk = 0; kk < 8; kk++) {
        uint32_t A0[4], A1[4], Bv[4], Bw[4];
        ldsm4(A0, aLane + kk * 32);
        ldsm4(A1, aLane + kk * 32 + 16 * UROWB);
        ldsm4(Bv, sb + UOFF_BH + bLane + kk * 32);
        ldsm4(Bw, sb + UOFF_BH + bLane + kk * 32 + 16 * UROWB);
        mma16816(a1[0][0], A0, Bv[0], Bv[1]); mma16816(a1[0][1], A0, Bv[2], Bv[3]);
        mma16816(a1[0][2], A0, Bw[0], Bw[1]); mma16816(a1[0][3], A0, Bw[2], Bw[3]);
        mma16816(a1[1][0], A1, Bv[0], Bv[1]); mma16816(a1[1][1], A1, Bv[2], Bv[3]);
        mma16816(a1[1][2], A1, Bw[0], Bw[1]); mma16816(a1[1][3], A1, Bw[2], Bw[3]);
        ldsm4(Bv, sb + UOFF_BL + bLane + kk * 32);
        ldsm4(Bw, sb + UOFF_BL + bLane + kk * 32 + 16 * UROWB);
        mma16816(a2[0][0], A0, Bv[0], Bv[1]); mma16816(a2[0][1], A0, Bv[2], Bv[3]);
        mma16816(a2[0][2], A0, Bw[0], Bw[1]); mma16816(a2[0][3], A0, Bw[2], Bw[3]);
        mma16816(a2[1][0], A1, Bv[0], Bv[1]); mma16816(a2[1][1], A1, Bv[2], Bv[3]);
        mma16816(a2[1][2], A1, Bw[0], Bw[1]); mma16816(a2[1][3], A1, Bw[2], Bw[3]);
    }
    __syncthreads();                     // done reading A/B; stage overlays them

    float (*stage)[132] = (float (*)[132])sm;   // [b 64][j 128]
    #pragma unroll
    for (int mt = 0; mt < 2; mt++)
        #pragma unroll
        for (int nt = 0; nt < 4; nt++) {
            int rb = mgb * 32 + mt * 16 + g8;
            int jc = njw * 32 + nt * 8 + tg * 2;
            stage[rb][jc]     = fmaf(kLoInv, a2[mt][nt][0], a1[mt][nt][0]);
            stage[rb][jc + 1] = fmaf(kLoInv, a2[mt][nt][1], a1[mt][nt][1]);
            stage[rb + 8][jc]     = fmaf(kLoInv, a2[mt][nt][2], a1[mt][nt][2]);
            stage[rb + 8][jc + 1] = fmaf(kLoInv, a2[mt][nt][3], a1[mt][nt][3]);
        }
    __syncthreads();

    #pragma unroll
    for (int rep = 0; rep < 8; rep++) {
        int b = wid * 8 + rep;
        #pragma unroll
        for (int c = 0; c < 4; c++) {
            int j = c * 32 + lane;
            float nv = noise[((size_t)b * Sn + (t - 1)) * Hn + j0 + j];
            stage[b][j] = fmaf(kAlpha, stage[b][j], kNoise * nv);
        }
    }
    __syncthreads();

    {
        int j = tid >> 1, bh = (tid & 1) * 32;
        #pragma unroll
        for (int bc = 0; bc < 8; bc++) {
            int b0 = bh + bc * 4;
            float4 v = make_float4(stage[b0][j], stage[b0 + 1][j],
                                   stage[b0 + 2][j], stage[b0 + 3][j]);
            *(float4*)&g_U[((size_t)t * Hn + j0 + j) * Bn + b0] = v;
        }
    }
}

// ---------------------------------------------------------------------------
// persistent HMMA loop. CTA (jt,kq): partial D[128j x 64b] over its k-slice.
// 8 compute warps: mg = wid>>1 (4 x 32j), nh = wid&1 (2 x 32b); each warp
// full k-slice, 4 ldsm + 8 mma per kk. Warps 8-15: loads + phase-2 only.
// ---------------------------------------------------------------------------
__global__ __launch_bounds__(NTHR, 1) void loop_kernel(const float* __restrict__ h0) {
    extern __shared__ char smem[];
    const uint32_t sb = smem_u32(smem);
    const int tid = threadIdx.x;
    const int wid = tid >> 5, lane = tid & 31;
    const int cta = blockIdx.x;
    const int jt = cta / KSPLIT, kq = cta % KSPLIT;
    const int j0 = jt * 128;
    const int ku = slice_units(kq);           // 14 or 15
    const int ku2 = ku * 2;                   // 16B chunks per row
    const int kbase = slice_start16(kq) * 16; // element base
    const int rc = cta * 16;                  // phase-2 j-base (cta < 128 only)

    const int mg = wid >> 1;                  // 0..3 (32 j each, compute warps)
    const int nh = wid & 1;                   // 0..1 (32 b each)
    const int g8 = lane >> 2, tg = lane & 3;

    // phase-2 ownership (fixed forever): j = rc + jl, b = bb..bb+1
    const int jl = (tid * 2) >> 6;            // 0..15
    const int bb = (tid * 2) & 63;
    const size_t ownIdx = (size_t)(rc + jl) * Bn + bb;
    float2 hreg = make_float2(0.f, 0.f);
    if (cta < 128) { float v = h0[rc + jl]; hreg = make_float2(v, v); }

    // ---- prologue: resident W -> SMEM (padded rows) ----
    for (int p = 0; p < 8; p++) {
        int f = tid + p * 512;                // < 4096
        int r = f >> 5, c = f & 31;
        if (c < ku2)
            *(uint4*)(smem + OFF_WH + r * ROWB + c * 16) =
                *(const uint4*)&g_Wh[(size_t)(j0 + r) * Hn + kbase + c * 8];
    }
    __syncthreads();

    const uint32_t aLane =
        sb + OFF_WH + (uint32_t)(mg * 32 + (lane & 15)) * ROWB + (lane >> 4) * 16;
    const uint32_t bLane =
        sb + OFF_BH + (uint32_t)(nh * 32 + (lane & 7) + ((lane >> 4) & 1) * 8) * ROWB +
        ((lane >> 3) & 1) * 16;
    float (*stage)[66] = (float (*)[66])(smem + OFF_STG);

    for (int t = 1; t < Sn; t++) {
        // ---- load B (fp16 h slice) ----
        #pragma unroll
        for (int p = 0; p < 4; p++) {
            int f = tid + p * 512;            // < 2048
            int b = f >> 5, c = f & 31;
            if (c < ku2)
                *(uint4*)(smem + OFF_BH + b * ROWB + c * 16) =
                    __ldcg((const uint4*)&g_hb[(size_t)b * Hn + kbase + c * 8]);
        }
        __syncthreads();

        // ---- single mma chain, full k-slice per compute warp ----
        float acc[2][4][4] = {};
        if (wid < 8) {
            #pragma unroll 5
            for (int kk = 0; kk < ku; kk++) {
                uint32_t A0[4], A1[4], Bv[4], Bw[4];
                ldsm4(A0, aLane + kk * 32);
                ldsm4(A1, aLane + kk * 32 + 16 * ROWB);
                ldsm4(Bv, bLane + kk * 32);
                ldsm4(Bw, bLane + kk * 32 + 16 * ROWB);
                mma16816(acc[0][0], A0, Bv[0], Bv[1]);
                mma16816(acc[0][1], A0, Bv[2], Bv[3]);
                mma16816(acc[0][2], A0, Bw[0], Bw[1]);
                mma16816(acc[0][3], A0, Bw[2], Bw[3]);
                mma16816(acc[1][0], A1, Bv[0], Bv[1]);
                mma16816(acc[1][1], A1, Bv[2], Bv[3]);
                mma16816(acc[1][2], A1, Bw[0], Bw[1]);
                mma16816(acc[1][3], A1, Bw[2], Bw[3]);
            }
        }
        __syncthreads();                      // done reading B (stage overlays)

        // ---- direct store to g_part (disjoint per compute warp) ----
        if (wid < 8) {
            #pragma unroll
            for (int mt = 0; mt < 2; mt++)
                #pragma unroll
                for (int nt = 0; nt < 4; nt++) {
                    int r0 = mt * 16 + g8, cc = nt * 8 + tg * 2;
                    int j = j0 + mg * 32 + r0;
                    int bc = nh * 32 + cc;
                    __stcg((float2*)&g_part[((size_t)kq * Hn + j) * Bn + bc],
                           make_float2(acc[mt][nt][0], acc[mt][nt][1]));
                    __stcg((float2*)&g_part[((size_t)kq * Hn + j + 8) * Bn + bc],
                           make_float2(acc[mt][nt][2], acc[mt][nt][3]));
                }
        }

        // ---- prefetch phase-2 U (barrier-independent) ----
        float2 uu = make_float2(0.f, 0.f);
        if (cta < 128) uu = *(const float2*)&g_U[(size_t)t * HB + ownIdx];

        grid_sync_dev();

        // ---- phase 2: reduce 9 k-slices + leak + U; CTAs 0..127 own 16 j each ----
        if (cta < 128) {
            float2 s = make_float2(0.f, 0.f);
            #pragma unroll
            for (int q = 0; q < KSPLIT; q++) {
                float2 v = __ldcg((const float2*)&g_part[(size_t)q * HB + ownIdx]);
                s.x += v.x; s.y += v.y;
            }
            hreg = make_float2((1.f - kAlpha) * hreg.x + s.x + uu.x,
                               (1.f - kAlpha) * hreg.y + s.y + uu.y);
            *(float2*)&stage[jl][bb] = hreg;
            __syncthreads();
            int b = tid >> 3, kk = tid & 7;
            __half2 hv;
            hv.x = __float2half_rn(stage[kk * 2][b]);
            hv.y = __float2half_rn(stage[kk * 2 + 1][b]);
            size_t off = (size_t)b * Hn + rc + kk * 2;
            *(__half2*)&g_hb[off] = hv;
            *(__half2*)&g_hist[(size_t)t * HB + off] = hv;
        }

        grid_sync_dev();
    }
}

// ---------------------------------------------------------------------------
// out[b][t][o] = sum_k g_hist[t][b][k] * woT[o][k]   (fp16 HMMA, one CTA per t)
// ---------------------------------------------------------------------------
__global__ __launch_bounds__(256) void out_kernel(float* __restrict__ out) {
    extern __shared__ char sm[];
    const uint32_t sb = smem_u32(sm);
    const int t = blockIdx.x, tid = threadIdx.x;
    const int wid = tid >> 5, lane = tid & 31;
    const int mg = wid >> 2, nh = wid & 3;

    const uint32_t aLane = (uint32_t)(mg * 32 + (lane & 15)) * ORB + (lane >> 4) * 16;
    const uint32_t bLane =
        (uint32_t)(nh * 32 + (lane & 7) + ((lane >> 4) & 1) * 8) * ORB +
        ((lane >> 3) & 1) * 16;
    const int g8 = lane >> 2, tg = lane & 3;

    float acc[2][4][4] = {};
    const __half* hsrc = g_hist + (size_t)t * HB;

    for (int k0 = 0; k0 < Hn; k0 += 128) {
        #pragma unroll
        for (int p = 0; p < 4; p++) {
            int f = tid + p * 256;
            int r = f >> 4, c = f & 15;
            *(uint4*)(sm + r * ORB + c * 16) =
                *(const uint4*)&hsrc[(size_t)r * Hn + k0 + c * 8];
        }
        #pragma unroll
        for (int p = 0; p < 8; p++) {
            int f = tid + p * 256;
            int r = f >> 4, c = f & 15;
            *(uint4*)(sm + OFF_OB + r * ORB + c * 16) =
                *(const uint4*)&g_woT[(size_t)r * Hn + k0 + c * 8];
        }
        __syncthreads();
        const uint32_t aB = sb + aLane, bB = sb + OFF_OB + bLane;
        #pragma unroll
        for (int kk = 0; kk < 8; kk++) {
            uint32_t A0[4], A1[4], Bv[4], Bw[4];
            ldsm4(A0, aB + kk * 32);
            ldsm4(A1, aB + kk * 32 + 16 * ORB);
            ldsm4(Bv, bB + kk * 32);
            ldsm4(Bw, bB + kk * 32 + 16 * ORB);
            mma16816(acc[0][0], A0, Bv[0], Bv[1]);
            mma16816(acc[0][1], A0, Bv[2], Bv[3]);
            mma16816(acc[0][2], A0, Bw[0], Bw[1]);
            mma16816(acc[0][3], A0, Bw[2], Bw[3]);
            mma16816(acc[1][0], A1, Bv[0], Bv[1]);
            mma16816(acc[1][1], A1, Bv[2], Bv[3]);
            mma16816(acc[1][2], A1, Bw[0], Bw[1]);
            mma16816(acc[1][3], A1, Bw[2], Bw[3]);
        }
        __syncthreads();
    }

    #pragma unroll
    for (int mt = 0; mt < 2; mt++)
        #pragma unroll
        for (int nt = 0; nt < 4; nt++) {
            int r0 = mt * 16 + g8, cc = nt * 8 + tg * 2;
            int b = mg * 32 + r0;
            int o = nh * 32 + cc;
            *(float2*)&out[((size_t)b * Sn + t) * On + o] =
                make_float2(acc[mt][nt][0], acc[mt][nt][1]);
            *(float2*)&out[((size_t)(b + 8) * Sn + t) * On + o] =
                make_float2(acc[mt][nt][2], acc[mt][nt][3]);
        }
}

// ---------------------------------------------------------------------------
extern "C" void kernel_launch(void* const* d_in, const int* in_sizes, int n_in,
                              void* d_out, int out_size) {
    const float* x     = (const float*)d_in[0];
    const float* noise = (const float*)d_in[1];
    const float* wi    = (const float*)d_in[2];
    const float* wrec  = (const float*)d_in[3];
    const float* wout  = (const float*)d_in[4];
    const float* g     = (const float*)d_in[5];
    const float* h0    = (const float*)d_in[6];
    float* out = (float*)d_out;

    cudaFuncSetAttribute(loop_kernel, cudaFuncAttributeMaxDynamicSharedMemorySize,
                         SMEM_TOTAL);
    cudaFuncSetAttribute(u_kernel, cudaFuncAttributeMaxDynamicSharedMemorySize,
                         USMEM);
    cudaFuncSetAttribute(out_kernel, cudaFuncAttributeMaxDynamicSharedMemorySize,
                         OSMEM);

    wprep_kernel<<<Hn * Hn / 256, 256>>>(wrec, g);
    wtprep_kernel<<<dim3(Hn / 32, On / 32), dim3(32, 32)>>>(wout);
    witprep_kernel<<<dim3(In / 32, Hn / 32), dim3(32, 32)>>>(wi);
    xhprep_kernel<<<Bn * Sn * In / 256, 256>>>(x);
    hbinit_kernel<<<HB / 256, 256>>>(h0);
    u_kernel<<<dim3(Hn / 128, Sn - 1), 256, USMEM>>>(noise);
    loop_kernel<<<NCTA, NTHR, SMEM_TOTAL>>>(h0);
    out_kernel<<<Sn, 256, OSMEM>>>(out);
}